// round 4
// baseline (speedup 1.0000x reference)
#include <cuda_runtime.h>
#include <cuda_bf16.h>
#include <cstdint>

#define BATCH 8
#define SQ    2048
#define SK    2048
#define DIM   256
#define MQ    (BATCH*SQ)

// ---------------- scratch (device globals; no runtime allocation) ----------
__device__ float g_scores[(size_t)BATCH * SQ * SK];
__device__ float g_Weff[DIM * DIM];
__device__ float g_beff[DIM];

__device__ __nv_bfloat16 g_xh[MQ * DIM],  g_xl[MQ * DIM];
__device__ __nv_bfloat16 g_sh[MQ * DIM],  g_sl[MQ * DIM];
__device__ __nv_bfloat16 g_Wqh[DIM * DIM], g_Wql[DIM * DIM];
__device__ __nv_bfloat16 g_Weh[DIM * DIM], g_Wel[DIM * DIM];
__device__ __nv_bfloat16 g_Wvh[DIM * DIM], g_Wvl[DIM * DIM];
__device__ __nv_bfloat16 g_qh[MQ * DIM],  g_ql[MQ * DIM];
__device__ __nv_bfloat16 g_wkh[MQ * DIM], g_wkl[MQ * DIM];
__device__ __nv_bfloat16 g_vTh[BATCH * DIM * SK], g_vTl[BATCH * DIM * SK];
__device__ __nv_bfloat16 g_Ph[(size_t)BATCH * SQ * SK], g_Pl[(size_t)BATCH * SQ * SK];

// ---------------- helpers ----------------
__device__ __forceinline__ uint32_t smem_u32(const void* p) {
    uint32_t a;
    asm("{ .reg .u64 t; cvta.to.shared.u64 t, %1; cvt.u32.u64 %0, t; }"
        : "=r"(a) : "l"(p));
    return a;
}

__device__ __forceinline__ void split2(float a, float b, uint32_t& h, uint32_t& l) {
    __nv_bfloat16 ha = __float2bfloat16(a), hb = __float2bfloat16(b);
    float la = a - __bfloat162float(ha);
    float lb = b - __bfloat162float(hb);
    h = (uint32_t)__bfloat16_as_ushort(ha) | ((uint32_t)__bfloat16_as_ushort(hb) << 16);
    l = (uint32_t)__bfloat16_as_ushort(__float2bfloat16(la)) |
        ((uint32_t)__bfloat16_as_ushort(__float2bfloat16(lb)) << 16);
}

#define CP_ASYNC16(dst, src) \
    asm volatile("cp.async.cg.shared.global [%0], [%1], 16;" \
                 :: "r"(dst), "l"(src) : "memory")
#define CP_COMMIT() asm volatile("cp.async.commit_group;" ::: "memory")
#define CP_WAIT1()  asm volatile("cp.async.wait_group 1;" ::: "memory")
#define CP_WAIT0()  asm volatile("cp.async.wait_group 0;" ::: "memory")

#define LDMATRIX_X4(r0, r1, r2, r3, addr)                                     \
    asm volatile("ldmatrix.sync.aligned.m8n8.x4.shared.b16 {%0,%1,%2,%3}, [%4];" \
                 : "=r"(r0), "=r"(r1), "=r"(r2), "=r"(r3) : "r"(addr))

#define MMA_BF16(c, a, b0, b1)                                                \
    asm volatile("mma.sync.aligned.m16n8k16.row.col.f32.bf16.bf16.f32 "       \
                 "{%0,%1,%2,%3}, {%4,%5,%6,%7}, {%8,%9}, {%0,%1,%2,%3};"      \
                 : "+f"((c)[0]), "+f"((c)[1]), "+f"((c)[2]), "+f"((c)[3])     \
                 : "r"((a)[0]), "r"((a)[1]), "r"((a)[2]), "r"((a)[3]),        \
                   "r"(b0), "r"(b1))

// 3-stage smem ring: each stage = A(16KB) + B(16KB)
#define STAGE_BYTES 32768
#define SMEM_BYTES  98304

// ================= bf16-split GEMM on mma.sync (HMMA) =================
// C[M,N](+bias) = Ah*Bh^T + Ah*Bl^T + Al*Bh^T
// A[M,K], B[N,K] row-major (K-major) bf16. CTA tile 128x128, BK=64.
// BIAS: 0 none, 1 per-col, 2 per-row.  SPLIT: 0 -> fp32 Cf, 1 -> bf16 Ch/Cl.
template <int BIAS, int SPLIT>
__global__ void __launch_bounds__(256, 2)
gemm_mma(const __nv_bfloat16* __restrict__ Ah, const __nv_bfloat16* __restrict__ Al,
         const __nv_bfloat16* __restrict__ Bh, const __nv_bfloat16* __restrict__ Bl,
         float* __restrict__ Cf, __nv_bfloat16* __restrict__ Ch,
         __nv_bfloat16* __restrict__ Cl, const float* __restrict__ bias,
         int K, long long sA, long long sB, long long sC, int ldc) {
    extern __shared__ __align__(128) char smem[];
    const uint32_t sb = smem_u32(smem);
    const int tid = threadIdx.x, lane = tid & 31, wid = tid >> 5;
    const int row0 = blockIdx.x * 128, col0 = blockIdx.y * 128;
    const long long z = blockIdx.z;
    Ah += z * sA; Al += z * sA; Bh += z * sB; Bl += z * sB;

    const int KT = K >> 6;     // 64-wide k-tiles per segment
    const int T  = 3 * KT;
    const size_t ldby = (size_t)K * 2;

    // loader indices (per thread: 4 x 16B for A, 4 x 16B for B)
    const int lrow = tid >> 1;            // 0..127 (row block of 128)
    const int lcol = (tid & 1) * 16;      // byte col 0 or 16
    (void)lrow; (void)lcol;

    auto load_tile = [&](int t, int stg) {
        const int seg = t / KT;
        const int kt  = t - seg * KT;
        const char* ga = (const char*)(((seg < 2) ? Ah : Al) + (size_t)row0 * K + kt * 64);
        const char* gb = (const char*)(((seg == 1) ? Bl : Bh) + (size_t)col0 * K + kt * 64);
        const uint32_t dA = sb + stg * STAGE_BYTES;
        const uint32_t dB = dA + 16384;
#pragma unroll
        for (int i = 0; i < 4; i++) {
            const int idx = i * 256 + tid;
            const int r = idx >> 3, c = (idx & 7) * 16;
            const uint32_t so = (uint32_t)(r * 128 + (c ^ ((r & 7) << 4)));
            CP_ASYNC16(dA + so, ga + (size_t)r * ldby + c);
            CP_ASYNC16(dB + so, gb + (size_t)r * ldby + c);
        }
        CP_COMMIT();
    };

    float acc[4][4][4];
#pragma unroll
    for (int i = 0; i < 4; i++)
#pragma unroll
        for (int j = 0; j < 4; j++)
#pragma unroll
            for (int e = 0; e < 4; e++) acc[i][j][e] = 0.f;

    // warp layout: 2 (m) x 4 (n); warp tile 64m x 32n
    const int wm0 = (wid & 1) * 64;
    const int wn0 = (wid >> 1) * 32;
    const uint32_t xr = (uint32_t)((lane & 7) << 4);
    const uint32_t aRow = (uint32_t)((wm0 + (lane & 15)) * 128);
    const uint32_t aK0  = (uint32_t)(((lane >> 4) & 1) * 16);
    const uint32_t bRow = (uint32_t)((wn0 + (((lane >> 3) & 2) << 2) + (lane & 7)) * 128);
    const uint32_t bK0  = (uint32_t)(((lane >> 3) & 1) * 16);

    auto compute = [&](int stg) {
        const uint32_t smA = sb + stg * STAGE_BYTES;
        const uint32_t smB = smA + 16384;
#pragma unroll
        for (int ks = 0; ks < 4; ks++) {
            uint32_t a[4][4], b[2][4];
#pragma unroll
            for (int mt = 0; mt < 4; mt++) {
                const uint32_t ad = smA + aRow + mt * 2048 + ((aK0 + ks * 32) ^ xr);
                LDMATRIX_X4(a[mt][0], a[mt][1], a[mt][2], a[mt][3], ad);
            }
#pragma unroll
            for (int np = 0; np < 2; np++) {
                const uint32_t bd = smB + bRow + np * 2048 + ((bK0 + ks * 32) ^ xr);
                LDMATRIX_X4(b[np][0], b[np][1], b[np][2], b[np][3], bd);
            }
#pragma unroll
            for (int mt = 0; mt < 4; mt++)
#pragma unroll
                for (int nt = 0; nt < 4; nt++)
                    MMA_BF16(acc[mt][nt], a[mt],
                             b[nt >> 1][(nt & 1) * 2], b[nt >> 1][(nt & 1) * 2 + 1]);
        }
    };

    // ---- 3-stage pipeline, one barrier per k-tile ----
    load_tile(0, 0);
    if (T > 1) load_tile(1, 1);
    int stg = 0;
    for (int t = 0; t < T; t++) {
        if (t + 1 < T) CP_WAIT1(); else CP_WAIT0();
        __syncthreads();   // tile t visible to all; all warps done reading buf of t-1
        if (t + 2 < T) {
            int s2 = stg + 2; if (s2 >= 3) s2 -= 3;
            load_tile(t + 2, s2);   // overwrites buffer compute(t-1) used: safe post-bar
        }
        compute(stg);
        if (++stg == 3) stg = 0;
    }

    // ---------------- epilogue ----------------
    const int bm = row0 + wm0 + (lane >> 2);
    const int bn = col0 + wn0 + (lane & 3) * 2;
#pragma unroll
    for (int mt = 0; mt < 4; mt++) {
#pragma unroll
        for (int nt = 0; nt < 4; nt++) {
            const int m = bm + mt * 16, n = bn + nt * 8;
            float c0 = acc[mt][nt][0], c1 = acc[mt][nt][1];
            float c2 = acc[mt][nt][2], c3 = acc[mt][nt][3];
            if (BIAS == 1) {
                const float b0v = bias[n], b1v = bias[n + 1];
                c0 += b0v; c1 += b1v; c2 += b0v; c3 += b1v;
            }
            if (BIAS == 2) {
                c0 += bias[m]; c1 += bias[m];
                c2 += bias[m + 8]; c3 += bias[m + 8];
            }
            if (SPLIT) {
                uint32_t h0, l0, h1, l1;
                split2(c0, c1, h0, l0);
                split2(c2, c3, h1, l1);
                __nv_bfloat16* oh = Ch + z * sC;
                __nv_bfloat16* ol = Cl + z * sC;
                *(uint32_t*)(oh + (size_t)m * ldc + n) = h0;
                *(uint32_t*)(ol + (size_t)m * ldc + n) = l0;
                *(uint32_t*)(oh + (size_t)(m + 8) * ldc + n) = h1;
                *(uint32_t*)(ol + (size_t)(m + 8) * ldc + n) = l1;
            } else {
                float* pc = Cf + z * sC;
                *(float2*)(pc + (size_t)m * ldc + n) = make_float2(c0, c1);
                *(float2*)(pc + (size_t)(m + 8) * ldc + n) = make_float2(c2, c3);
            }
        }
    }
}

// ---------------- fused-weight prep: Weff = Wa @ Wk, beff = Wa@bk + ba ----
__global__ void weff_kernel(const float* __restrict__ Wa,
                            const float* __restrict__ Wk,
                            const float* __restrict__ bk,
                            const float* __restrict__ ba,
                            float* __restrict__ Weff,
                            float* __restrict__ beff) {
    const int e = blockIdx.x;
    const int t = threadIdx.x;
    __shared__ float wa[DIM];
    wa[t] = Wa[e * DIM + t];
    __syncthreads();
    float acc = 0.f;
#pragma unroll 8
    for (int j = 0; j < DIM; j++)
        acc = fmaf(wa[j], Wk[j * DIM + t], acc);
    Weff[e * DIM + t] = acc;

    float pb = wa[t] * bk[t];
#pragma unroll
    for (int o = 16; o; o >>= 1)
        pb += __shfl_xor_sync(0xffffffffu, pb, o);
    __shared__ float red[8];
    if ((t & 31) == 0) red[t >> 5] = pb;
    __syncthreads();
    if (t == 0) {
        float s = 0.f;
#pragma unroll
        for (int i = 0; i < 8; i++) s += red[i];
        beff[e] = s + ba[e];
    }
}

// ---------------- fp32 -> (hi, lo) bf16 split ----------------
__global__ void split_kernel(const float* __restrict__ in,
                             __nv_bfloat16* __restrict__ h,
                             __nv_bfloat16* __restrict__ l, int n4) {
    int i = blockIdx.x * blockDim.x + threadIdx.x;
    if (i >= n4) return;
    float4 v = *(const float4*)(in + 4 * (size_t)i);
    uint32_t h0, l0, h1, l1;
    split2(v.x, v.y, h0, l0);
    split2(v.z, v.w, h1, l1);
    *(uint2*)(h + 4 * (size_t)i) = make_uint2(h0, h1);
    *(uint2*)(l + 4 * (size_t)i) = make_uint2(l0, l1);
}

// ---------------- softmax over 2048-wide rows, emits bf16 split ----------
__global__ void softmax_split(const float* __restrict__ S,
                              __nv_bfloat16* __restrict__ Ph,
                              __nv_bfloat16* __restrict__ Pl) {
    const size_t row = blockIdx.x;
    const float4* p4 = (const float4*)(S + row * (size_t)SK);
    const int t = threadIdx.x;

    float4 u0 = p4[t];
    float4 u1 = p4[t + 256];
    float v[8] = {u0.x, u0.y, u0.z, u0.w, u1.x, u1.y, u1.z, u1.w};

    float m = v[0];
#pragma unroll
    for (int i = 1; i < 8; i++) m = fmaxf(m, v[i]);
#pragma unroll
    for (int o = 16; o; o >>= 1) m = fmaxf(m, __shfl_xor_sync(0xffffffffu, m, o));

    __shared__ float red[8];
    const int w = t >> 5, l = t & 31;
    if (l == 0) red[w] = m;
    __syncthreads();
    float mm = red[0];
#pragma unroll
    for (int i = 1; i < 8; i++) mm = fmaxf(mm, red[i]);

    float s = 0.f;
#pragma unroll
    for (int i = 0; i < 8; i++) {
        v[i] = __expf(v[i] - mm);
        s += v[i];
    }
#pragma unroll
    for (int o = 16; o; o >>= 1) s += __shfl_xor_sync(0xffffffffu, s, o);
    __syncthreads();
    if (l == 0) red[w] = s;
    __syncthreads();
    float ss = red[0];
#pragma unroll
    for (int i = 1; i < 8; i++) ss += red[i];
    const float inv = 1.0f / ss;

    __nv_bfloat16* bh = Ph + row * (size_t)SK;
    __nv_bfloat16* bl = Pl + row * (size_t)SK;
#pragma unroll
    for (int half = 0; half < 2; half++) {
        const int c = (half ? (t + 256) : t) * 4;
        uint32_t h0, l0, h1, l1;
        split2(v[half * 4 + 0] * inv, v[half * 4 + 1] * inv, h0, l0);
        split2(v[half * 4 + 2] * inv, v[half * 4 + 3] * inv, h1, l1);
        *(uint2*)(bh + c) = make_uint2(h0, h1);
        *(uint2*)(bl + c) = make_uint2(l0, l1);
    }
}

// ---------------- launcher ----------------
extern "C" void kernel_launch(void* const* d_in, const int* in_sizes, int n_in,
                              void* d_out, int out_size) {
    const float* x      = (const float*)d_in[0];
    const float* states = (const float*)d_in[1];
    const float* Wq = (const float*)d_in[2];
    const float* bq = (const float*)d_in[3];
    const float* Wk = (const float*)d_in[4];
    const float* bk = (const float*)d_in[5];
    const float* Wv = (const float*)d_in[6];
    const float* bv = (const float*)d_in[7];
    const float* Wa = (const float*)d_in[8];
    const float* ba = (const float*)d_in[9];
    float* out = (float*)d_out;

    float *sc, *weff, *beff;
    __nv_bfloat16 *xh, *xl, *sh, *sl, *Wqh, *Wql, *Weh, *Wel, *Wvh, *Wvl;
    __nv_bfloat16 *qh, *ql, *wkh, *wkl, *vTh, *vTl, *Ph, *Pl;
    cudaGetSymbolAddress((void**)&sc,   g_scores);
    cudaGetSymbolAddress((void**)&weff, g_Weff);
    cudaGetSymbolAddress((void**)&beff, g_beff);
    cudaGetSymbolAddress((void**)&xh,  g_xh);   cudaGetSymbolAddress((void**)&xl,  g_xl);
    cudaGetSymbolAddress((void**)&sh,  g_sh);   cudaGetSymbolAddress((void**)&sl,  g_sl);
    cudaGetSymbolAddress((void**)&Wqh, g_Wqh);  cudaGetSymbolAddress((void**)&Wql, g_Wql);
    cudaGetSymbolAddress((void**)&Weh, g_Weh);  cudaGetSymbolAddress((void**)&Wel, g_Wel);
    cudaGetSymbolAddress((void**)&Wvh, g_Wvh);  cudaGetSymbolAddress((void**)&Wvl, g_Wvl);
    cudaGetSymbolAddress((void**)&qh,  g_qh);   cudaGetSymbolAddress((void**)&ql,  g_ql);
    cudaGetSymbolAddress((void**)&wkh, g_wkh);  cudaGetSymbolAddress((void**)&wkl, g_wkl);
    cudaGetSymbolAddress((void**)&vTh, g_vTh);  cudaGetSymbolAddress((void**)&vTl, g_vTl);
    cudaGetSymbolAddress((void**)&Ph,  g_Ph);   cudaGetSymbolAddress((void**)&Pl,  g_Pl);

    cudaFuncSetAttribute(gemm_mma<0,0>, cudaFuncAttributeMaxDynamicSharedMemorySize, SMEM_BYTES);
    cudaFuncSetAttribute(gemm_mma<1,1>, cudaFuncAttributeMaxDynamicSharedMemorySize, SMEM_BYTES);
    cudaFuncSetAttribute(gemm_mma<2,1>, cudaFuncAttributeMaxDynamicSharedMemorySize, SMEM_BYTES);

    // 1) fold Wa into the K projection (fp32)
    weff_kernel<<<DIM, DIM>>>(Wa, Wk, bk, ba, weff, beff);

    // 2) bf16 splits of activations and weights
    split_kernel<<<(MQ * DIM / 4 + 255) / 256, 256>>>(x,      xh,  xl,  MQ * DIM / 4);
    split_kernel<<<(MQ * DIM / 4 + 255) / 256, 256>>>(states, sh,  sl,  MQ * DIM / 4);
    split_kernel<<<(DIM * DIM / 4 + 255) / 256, 256>>>(Wq,   Wqh, Wql, DIM * DIM / 4);
    split_kernel<<<(DIM * DIM / 4 + 255) / 256, 256>>>(Wv,   Wvh, Wvl, DIM * DIM / 4);
    split_kernel<<<(DIM * DIM / 4 + 255) / 256, 256>>>(weff, Weh, Wel, DIM * DIM / 4);

    // 3) linears on tensor cores (outputs split to bf16 h/l)
    gemm_mma<1,1><<<dim3(MQ / 128, DIM / 128, 1), 256, SMEM_BYTES>>>(
        xh, xl, Wqh, Wql, nullptr, qh, ql, bq, DIM, 0, 0, 0, DIM);
    gemm_mma<1,1><<<dim3(MQ / 128, DIM / 128, 1), 256, SMEM_BYTES>>>(
        sh, sl, Weh, Wel, nullptr, wkh, wkl, beff, DIM, 0, 0, 0, DIM);
    //    vT = Wv @ states^T + bv(row) per batch -> [256, 2048] x 8
    gemm_mma<2,1><<<dim3(DIM / 128, SK / 128, BATCH), 256, SMEM_BYTES>>>(
        Wvh, Wvl, sh, sl, nullptr, vTh, vTl, bv, DIM,
        0, (long long)SK * DIM, (long long)DIM * SK, SK);

    // 4) scores = q @ wk^T per batch  [2048, 2048] x 8, fp32 out
    gemm_mma<0,0><<<dim3(SQ / 128, SK / 128, BATCH), 256, SMEM_BYTES>>>(
        qh, ql, wkh, wkl, sc, nullptr, nullptr, nullptr, DIM,
        (long long)SQ * DIM, (long long)SK * DIM, (long long)SQ * SK, SK);

    // 5) softmax + bf16 split of probabilities
    softmax_split<<<MQ, 256>>>(sc, Ph, Pl);

    // 6) context = P @ vT^T per batch -> out [2048, 256] x 8, fp32
    gemm_mma<0,0><<<dim3(SQ / 128, DIM / 128, BATCH), 256, SMEM_BYTES>>>(
        Ph, Pl, vTh, vTl, out, nullptr, nullptr, nullptr, SK,
        (long long)SQ * SK, (long long)DIM * SK, (long long)SQ * DIM, DIM);
}

// round 5
// speedup vs baseline: 1.5674x; 1.5674x over previous
#include <cuda_runtime.h>
#include <cuda_bf16.h>
#include <cstdint>

#define BATCH 8
#define SQ    2048
#define SK    2048
#define DIM   256
#define MQ    (BATCH*SQ)

// ---------------- scratch (device globals; no runtime allocation) ----------
__device__ float g_scores[(size_t)BATCH * SQ * SK];
__device__ float g_beff[DIM];

__device__ __nv_bfloat16 g_xh[MQ * DIM],  g_xl[MQ * DIM];
__device__ __nv_bfloat16 g_sh[MQ * DIM],  g_sl[MQ * DIM];
__device__ __nv_bfloat16 g_Wqh[DIM * DIM], g_Wql[DIM * DIM];
__device__ __nv_bfloat16 g_Weh[DIM * DIM], g_Wel[DIM * DIM];
__device__ __nv_bfloat16 g_Wvh[DIM * DIM], g_Wvl[DIM * DIM];
__device__ __nv_bfloat16 g_qh[MQ * DIM],  g_ql[MQ * DIM];
__device__ __nv_bfloat16 g_wkh[MQ * DIM], g_wkl[MQ * DIM];
__device__ __nv_bfloat16 g_vTh[BATCH * DIM * SK], g_vTl[BATCH * DIM * SK];
__device__ __nv_bfloat16 g_Ph[(size_t)BATCH * SQ * SK], g_Pl[(size_t)BATCH * SQ * SK];

// ---------------- helpers ----------------
__device__ __forceinline__ uint32_t smem_u32(const void* p) {
    uint32_t a;
    asm("{ .reg .u64 t; cvta.to.shared.u64 t, %1; cvt.u32.u64 %0, t; }"
        : "=r"(a) : "l"(p));
    return a;
}

__device__ __forceinline__ void split2(float a, float b, uint32_t& h, uint32_t& l) {
    __nv_bfloat16 ha = __float2bfloat16(a), hb = __float2bfloat16(b);
    float la = a - __bfloat162float(ha);
    float lb = b - __bfloat162float(hb);
    h = (uint32_t)__bfloat16_as_ushort(ha) | ((uint32_t)__bfloat16_as_ushort(hb) << 16);
    l = (uint32_t)__bfloat16_as_ushort(__float2bfloat16(la)) |
        ((uint32_t)__bfloat16_as_ushort(__float2bfloat16(lb)) << 16);
}

#define CP_ASYNC16(dst, src) \
    asm volatile("cp.async.cg.shared.global [%0], [%1], 16;" \
                 :: "r"(dst), "l"(src) : "memory")
#define CP_COMMIT() asm volatile("cp.async.commit_group;" ::: "memory")
#define CP_WAIT1()  asm volatile("cp.async.wait_group 1;" ::: "memory")
#define CP_WAIT0()  asm volatile("cp.async.wait_group 0;" ::: "memory")

#define LDMATRIX_X4(r0, r1, r2, r3, addr)                                     \
    asm volatile("ldmatrix.sync.aligned.m8n8.x4.shared.b16 {%0,%1,%2,%3}, [%4];" \
                 : "=r"(r0), "=r"(r1), "=r"(r2), "=r"(r3) : "r"(addr))

#define MMA_BF16(c, a, b0, b1)                                                \
    asm volatile("mma.sync.aligned.m16n8k16.row.col.f32.bf16.bf16.f32 "       \
                 "{%0,%1,%2,%3}, {%4,%5,%6,%7}, {%8,%9}, {%0,%1,%2,%3};"      \
                 : "+f"((c)[0]), "+f"((c)[1]), "+f"((c)[2]), "+f"((c)[3])     \
                 : "r"((a)[0]), "r"((a)[1]), "r"((a)[2]), "r"((a)[3]),        \
                   "r"(b0), "r"(b1))

// 2 stages; each stage = slot0(16KB) + slot1(16KB) + slot2(16KB)
#define STAGE_BYTES 49152
#define SMEM_BYTES  98304

// ================= bf16-split GEMM on mma.sync (HMMA) =================
// C = Ah*Bh^T + Ah*Bl^T + Al*Bh^T   (+bias)
// Phase 1 chunks: load {Ah, Bh, Bl}, compute Ah*Bh + Ah*Bl (A frags reused).
// Phase 2 chunks: load {Al, Bh},      compute Al*Bh.
// A[M,K], B[N,K] row-major bf16. CTA tile 128x128, BK=64.
// BIAS: 0 none, 1 per-col, 2 per-row.  SPLIT: 0 -> fp32 Cf, 1 -> bf16 Ch/Cl.
template <int BIAS, int SPLIT>
__global__ void __launch_bounds__(256)
gemm_mma(const __nv_bfloat16* __restrict__ Ah, const __nv_bfloat16* __restrict__ Al,
         const __nv_bfloat16* __restrict__ Bh, const __nv_bfloat16* __restrict__ Bl,
         float* __restrict__ Cf, __nv_bfloat16* __restrict__ Ch,
         __nv_bfloat16* __restrict__ Cl, const float* __restrict__ bias,
         int K, long long sA, long long sB, long long sC, int ldc) {
    extern __shared__ __align__(128) char smem[];
    const uint32_t sb = smem_u32(smem);
    const int tid = threadIdx.x, lane = tid & 31, wid = tid >> 5;
    const int row0 = blockIdx.x * 128, col0 = blockIdx.y * 128;
    const long long z = blockIdx.z;
    Ah += z * sA; Al += z * sA; Bh += z * sB; Bl += z * sB;

    const int KT = K >> 6;       // 64-wide k-chunks per phase
    const int T  = 2 * KT;       // phase1 chunks then phase2 chunks
    const size_t ldby = (size_t)K * 2;

    // one 16KB tile: 128 rows x 128B, 4 x 16B per thread
    auto load_one = [&](const char* g, uint32_t dst) {
#pragma unroll
        for (int i = 0; i < 4; i++) {
            const int idx = i * 256 + tid;
            const int r = idx >> 3, c = (idx & 7) * 16;
            const uint32_t so = (uint32_t)(r * 128 + (c ^ ((r & 7) << 4)));
            CP_ASYNC16(dst + so, g + (size_t)r * ldby + c);
        }
    };

    auto load_chunk = [&](int t, int p) {
        const uint32_t base = sb + p * STAGE_BYTES;
        if (t < KT) {
            const int kt = t;
            load_one((const char*)(Ah + (size_t)row0 * K + kt * 64), base);
            load_one((const char*)(Bh + (size_t)col0 * K + kt * 64), base + 16384);
            load_one((const char*)(Bl + (size_t)col0 * K + kt * 64), base + 32768);
        } else {
            const int kt = t - KT;
            load_one((const char*)(Al + (size_t)row0 * K + kt * 64), base);
            load_one((const char*)(Bh + (size_t)col0 * K + kt * 64), base + 16384);
        }
        CP_COMMIT();
    };

    float acc[4][4][4];
#pragma unroll
    for (int i = 0; i < 4; i++)
#pragma unroll
        for (int j = 0; j < 4; j++)
#pragma unroll
            for (int e = 0; e < 4; e++) acc[i][j][e] = 0.f;

    // warp layout: 2 (m) x 4 (n); warp tile 64m x 32n
    const int wm0 = (wid & 1) * 64;
    const int wn0 = (wid >> 1) * 32;
    const uint32_t xr = (uint32_t)((lane & 7) << 4);
    const uint32_t aRow = (uint32_t)((wm0 + (lane & 15)) * 128);
    const uint32_t aK0  = (uint32_t)(((lane >> 4) & 1) * 16);
    const uint32_t bRow = (uint32_t)((wn0 + (((lane >> 3) & 2) << 2) + (lane & 7)) * 128);
    const uint32_t bK0  = (uint32_t)(((lane >> 3) & 1) * 16);

    // phase 1: A frags reused for both B operands
    auto compute1 = [&](int p) {
        const uint32_t smA  = sb + p * STAGE_BYTES;
        const uint32_t smBh = smA + 16384;
        const uint32_t smBl = smA + 32768;
#pragma unroll
        for (int ks = 0; ks < 4; ks++) {
            uint32_t a[4][4], bh[2][4], bl[2][4];
#pragma unroll
            for (int mt = 0; mt < 4; mt++) {
                const uint32_t ad = smA + aRow + mt * 2048 + ((aK0 + ks * 32) ^ xr);
                LDMATRIX_X4(a[mt][0], a[mt][1], a[mt][2], a[mt][3], ad);
            }
#pragma unroll
            for (int np = 0; np < 2; np++) {
                const uint32_t off = bRow + np * 2048 + ((bK0 + ks * 32) ^ xr);
                LDMATRIX_X4(bh[np][0], bh[np][1], bh[np][2], bh[np][3], smBh + off);
                LDMATRIX_X4(bl[np][0], bl[np][1], bl[np][2], bl[np][3], smBl + off);
            }
#pragma unroll
            for (int mt = 0; mt < 4; mt++)
#pragma unroll
                for (int nt = 0; nt < 4; nt++) {
                    MMA_BF16(acc[mt][nt], a[mt],
                             bh[nt >> 1][(nt & 1) * 2], bh[nt >> 1][(nt & 1) * 2 + 1]);
                    MMA_BF16(acc[mt][nt], a[mt],
                             bl[nt >> 1][(nt & 1) * 2], bl[nt >> 1][(nt & 1) * 2 + 1]);
                }
        }
    };

    // phase 2: single term Al*Bh (same as R3 compute)
    auto compute2 = [&](int p) {
        const uint32_t smA  = sb + p * STAGE_BYTES;
        const uint32_t smBh = smA + 16384;
#pragma unroll
        for (int ks = 0; ks < 4; ks++) {
            uint32_t a[4][4], b[2][4];
#pragma unroll
            for (int mt = 0; mt < 4; mt++) {
                const uint32_t ad = smA + aRow + mt * 2048 + ((aK0 + ks * 32) ^ xr);
                LDMATRIX_X4(a[mt][0], a[mt][1], a[mt][2], a[mt][3], ad);
            }
#pragma unroll
            for (int np = 0; np < 2; np++) {
                const uint32_t bd = smBh + bRow + np * 2048 + ((bK0 + ks * 32) ^ xr);
                LDMATRIX_X4(b[np][0], b[np][1], b[np][2], b[np][3], bd);
            }
#pragma unroll
            for (int mt = 0; mt < 4; mt++)
#pragma unroll
                for (int nt = 0; nt < 4; nt++)
                    MMA_BF16(acc[mt][nt], a[mt],
                             b[nt >> 1][(nt & 1) * 2], b[nt >> 1][(nt & 1) * 2 + 1]);
        }
    };

    // ---- R3-style pipeline: 2 stages, static p = t&1, load-then-wait ----
    load_chunk(0, 0);
    for (int t = 0; t < T; t++) {
        const int p = t & 1;
        if (t + 1 < T) {
            load_chunk(t + 1, p ^ 1);
            CP_WAIT1();
        } else {
            CP_WAIT0();
        }
        __syncthreads();
        if (t < KT) compute1(p); else compute2(p);
        __syncthreads();
    }

    // ---------------- epilogue ----------------
    const int bm = row0 + wm0 + (lane >> 2);
    const int bn = col0 + wn0 + (lane & 3) * 2;
#pragma unroll
    for (int mt = 0; mt < 4; mt++) {
#pragma unroll
        for (int nt = 0; nt < 4; nt++) {
            const int m = bm + mt * 16, n = bn + nt * 8;
            float c0 = acc[mt][nt][0], c1 = acc[mt][nt][1];
            float c2 = acc[mt][nt][2], c3 = acc[mt][nt][3];
            if (BIAS == 1) {
                const float b0v = bias[n], b1v = bias[n + 1];
                c0 += b0v; c1 += b1v; c2 += b0v; c3 += b1v;
            }
            if (BIAS == 2) {
                c0 += bias[m]; c1 += bias[m];
                c2 += bias[m + 8]; c3 += bias[m + 8];
            }
            if (SPLIT) {
                uint32_t h0, l0, h1, l1;
                split2(c0, c1, h0, l0);
                split2(c2, c3, h1, l1);
                __nv_bfloat16* oh = Ch + z * sC;
                __nv_bfloat16* ol = Cl + z * sC;
                *(uint32_t*)(oh + (size_t)m * ldc + n) = h0;
                *(uint32_t*)(ol + (size_t)m * ldc + n) = l0;
                *(uint32_t*)(oh + (size_t)(m + 8) * ldc + n) = h1;
                *(uint32_t*)(ol + (size_t)(m + 8) * ldc + n) = l1;
            } else {
                float* pc = Cf + z * sC;
                *(float2*)(pc + (size_t)m * ldc + n) = make_float2(c0, c1);
                *(float2*)(pc + (size_t)(m + 8) * ldc + n) = make_float2(c2, c3);
            }
        }
    }
}

// ---------------- fused-weight prep: Weff = Wa @ Wk (bf16-split out) ------
__global__ void weff_kernel(const float* __restrict__ Wa,
                            const float* __restrict__ Wk,
                            const float* __restrict__ bk,
                            const float* __restrict__ ba,
                            __nv_bfloat16* __restrict__ Weh,
                            __nv_bfloat16* __restrict__ Wel,
                            float* __restrict__ beff) {
    const int e = blockIdx.x;
    const int t = threadIdx.x;
    __shared__ float wa[DIM];
    wa[t] = Wa[e * DIM + t];
    __syncthreads();
    float acc = 0.f;
#pragma unroll 8
    for (int j = 0; j < DIM; j++)
        acc = fmaf(wa[j], Wk[j * DIM + t], acc);
    __nv_bfloat16 hi = __float2bfloat16(acc);
    Weh[e * DIM + t] = hi;
    Wel[e * DIM + t] = __float2bfloat16(acc - __bfloat162float(hi));

    float pb = wa[t] * bk[t];
#pragma unroll
    for (int o = 16; o; o >>= 1)
        pb += __shfl_xor_sync(0xffffffffu, pb, o);
    __shared__ float red[8];
    if ((t & 31) == 0) red[t >> 5] = pb;
    __syncthreads();
    if (t == 0) {
        float s = 0.f;
#pragma unroll
        for (int i = 0; i < 8; i++) s += red[i];
        beff[e] = s + ba[e];
    }
}

// ---------------- merged fp32 -> (hi,lo) bf16 split for 4 tensors ----------
// regions (in blocks of 256 thr x 4 f32): x, states, Wq, Wv
#define NB_ACT (MQ * DIM / 4 / 256)     // 4096 blocks
#define NB_W   (DIM * DIM / 4 / 256)    // 64 blocks
__global__ void split4_kernel(const float* __restrict__ x,   __nv_bfloat16* xh, __nv_bfloat16* xl,
                              const float* __restrict__ st,  __nv_bfloat16* sh, __nv_bfloat16* sl,
                              const float* __restrict__ wq,  __nv_bfloat16* qh, __nv_bfloat16* ql,
                              const float* __restrict__ wv,  __nv_bfloat16* vh, __nv_bfloat16* vl) {
    int b = blockIdx.x;
    const float* in; __nv_bfloat16 *h, *l;
    if (b < NB_ACT)                   { in = x;  h = xh; l = xl; }
    else if ((b -= NB_ACT) < NB_ACT)  { in = st; h = sh; l = sl; }
    else if ((b -= NB_ACT) < NB_W)    { in = wq; h = qh; l = ql; }
    else { b -= NB_W;                   in = wv; h = vh; l = vl; }
    const size_t i = (size_t)b * 256 + threadIdx.x;
    float4 v = *(const float4*)(in + 4 * i);
    uint32_t h0, l0, h1, l1;
    split2(v.x, v.y, h0, l0);
    split2(v.z, v.w, h1, l1);
    *(uint2*)(h + 4 * i) = make_uint2(h0, h1);
    *(uint2*)(l + 4 * i) = make_uint2(l0, l1);
}

// ---------------- softmax over 2048-wide rows, emits bf16 split ----------
__global__ void softmax_split(const float* __restrict__ S,
                              __nv_bfloat16* __restrict__ Ph,
                              __nv_bfloat16* __restrict__ Pl) {
    const size_t row = blockIdx.x;
    const float4* p4 = (const float4*)(S + row * (size_t)SK);
    const int t = threadIdx.x;

    float4 u0 = p4[t];
    float4 u1 = p4[t + 256];
    float v[8] = {u0.x, u0.y, u0.z, u0.w, u1.x, u1.y, u1.z, u1.w};

    float m = v[0];
#pragma unroll
    for (int i = 1; i < 8; i++) m = fmaxf(m, v[i]);
#pragma unroll
    for (int o = 16; o; o >>= 1) m = fmaxf(m, __shfl_xor_sync(0xffffffffu, m, o));

    __shared__ float red[8];
    const int w = t >> 5, l = t & 31;
    if (l == 0) red[w] = m;
    __syncthreads();
    float mm = red[0];
#pragma unroll
    for (int i = 1; i < 8; i++) mm = fmaxf(mm, red[i]);

    float s = 0.f;
#pragma unroll
    for (int i = 0; i < 8; i++) {
        v[i] = __expf(v[i] - mm);
        s += v[i];
    }
#pragma unroll
    for (int o = 16; o; o >>= 1) s += __shfl_xor_sync(0xffffffffu, s, o);
    __syncthreads();
    if (l == 0) red[w] = s;
    __syncthreads();
    float ss = red[0];
#pragma unroll
    for (int i = 1; i < 8; i++) ss += red[i];
    const float inv = 1.0f / ss;

    __nv_bfloat16* bh = Ph + row * (size_t)SK;
    __nv_bfloat16* bl = Pl + row * (size_t)SK;
#pragma unroll
    for (int half = 0; half < 2; half++) {
        const int c = (half ? (t + 256) : t) * 4;
        uint32_t h0, l0, h1, l1;
        split2(v[half * 4 + 0] * inv, v[half * 4 + 1] * inv, h0, l0);
        split2(v[half * 4 + 2] * inv, v[half * 4 + 3] * inv, h1, l1);
        *(uint2*)(bh + c) = make_uint2(h0, h1);
        *(uint2*)(bl + c) = make_uint2(l0, l1);
    }
}

// ---------------- launcher ----------------
extern "C" void kernel_launch(void* const* d_in, const int* in_sizes, int n_in,
                              void* d_out, int out_size) {
    const float* x      = (const float*)d_in[0];
    const float* states = (const float*)d_in[1];
    const float* Wq = (const float*)d_in[2];
    const float* bq = (const float*)d_in[3];
    const float* Wk = (const float*)d_in[4];
    const float* bk = (const float*)d_in[5];
    const float* Wv = (const float*)d_in[6];
    const float* bv = (const float*)d_in[7];
    const float* Wa = (const float*)d_in[8];
    const float* ba = (const float*)d_in[9];
    float* out = (float*)d_out;

    float *sc, *beff;
    __nv_bfloat16 *xh, *xl, *sh, *sl, *Wqh, *Wql, *Weh, *Wel, *Wvh, *Wvl;
    __nv_bfloat16 *qh, *ql, *wkh, *wkl, *vTh, *vTl, *Ph, *Pl;
    cudaGetSymbolAddress((void**)&sc,   g_scores);
    cudaGetSymbolAddress((void**)&beff, g_beff);
    cudaGetSymbolAddress((void**)&xh,  g_xh);   cudaGetSymbolAddress((void**)&xl,  g_xl);
    cudaGetSymbolAddress((void**)&sh,  g_sh);   cudaGetSymbolAddress((void**)&sl,  g_sl);
    cudaGetSymbolAddress((void**)&Wqh, g_Wqh);  cudaGetSymbolAddress((void**)&Wql, g_Wql);
    cudaGetSymbolAddress((void**)&Weh, g_Weh);  cudaGetSymbolAddress((void**)&Wel, g_Wel);
    cudaGetSymbolAddress((void**)&Wvh, g_Wvh);  cudaGetSymbolAddress((void**)&Wvl, g_Wvl);
    cudaGetSymbolAddress((void**)&qh,  g_qh);   cudaGetSymbolAddress((void**)&ql,  g_ql);
    cudaGetSymbolAddress((void**)&wkh, g_wkh);  cudaGetSymbolAddress((void**)&wkl, g_wkl);
    cudaGetSymbolAddress((void**)&vTh, g_vTh);  cudaGetSymbolAddress((void**)&vTl, g_vTl);
    cudaGetSymbolAddress((void**)&Ph,  g_Ph);   cudaGetSymbolAddress((void**)&Pl,  g_Pl);

    cudaFuncSetAttribute(gemm_mma<0,0>, cudaFuncAttributeMaxDynamicSharedMemorySize, SMEM_BYTES);
    cudaFuncSetAttribute(gemm_mma<1,1>, cudaFuncAttributeMaxDynamicSharedMemorySize, SMEM_BYTES);
    cudaFuncSetAttribute(gemm_mma<2,1>, cudaFuncAttributeMaxDynamicSharedMemorySize, SMEM_BYTES);

    // 1) fold Wa into the K projection (fp32 -> split bf16 directly)
    weff_kernel<<<DIM, DIM>>>(Wa, Wk, bk, ba, Weh, Wel, beff);

    // 2) bf16 splits of x, states, Wq, Wv in one launch
    split4_kernel<<<2 * NB_ACT + 2 * NB_W, 256>>>(
        x, xh, xl, states, sh, sl, Wq, Wqh, Wql, Wv, Wvh, Wvl);

    // 3) linears on tensor cores (outputs split to bf16 h/l)
    gemm_mma<1,1><<<dim3(MQ / 128, DIM / 128, 1), 256, SMEM_BYTES>>>(
        xh, xl, Wqh, Wql, nullptr, qh, ql, bq, DIM, 0, 0, 0, DIM);
    gemm_mma<1,1><<<dim3(MQ / 128, DIM / 128, 1), 256, SMEM_BYTES>>>(
        sh, sl, Weh, Wel, nullptr, wkh, wkl, beff, DIM, 0, 0, 0, DIM);
    //    vT = Wv @ states^T + bv(row) per batch -> [256, 2048] x 8
    gemm_mma<2,1><<<dim3(DIM / 128, SK / 128, BATCH), 256, SMEM_BYTES>>>(
        Wvh, Wvl, sh, sl, nullptr, vTh, vTl, bv, DIM,
        0, (long long)SK * DIM, (long long)DIM * SK, SK);

    // 4) scores = q @ wk^T per batch  [2048, 2048] x 8, fp32 out
    gemm_mma<0,0><<<dim3(SQ / 128, SK / 128, BATCH), 256, SMEM_BYTES>>>(
        qh, ql, wkh, wkl, sc, nullptr, nullptr, nullptr, DIM,
        (long long)SQ * DIM, (long long)SK * DIM, (long long)SQ * SK, SK);

    // 5) softmax + bf16 split of probabilities
    softmax_split<<<MQ, 256>>>(sc, Ph, Pl);

    // 6) context = P @ vT^T per batch -> out [2048, 256] x 8, fp32
    gemm_mma<0,0><<<dim3(SQ / 128, DIM / 128, BATCH), 256, SMEM_BYTES>>>(
        Ph, Pl, vTh, vTl, out, nullptr, nullptr, nullptr, SK,
        (long long)SQ * SK, (long long)DIM * SK, (long long)SQ * DIM, DIM);
}